// round 5
// baseline (speedup 1.0000x reference)
#include <cuda_runtime.h>
#include <cuda_fp16.h>
#include <cstdint>

// ============================================================================
// y = x @ W^T + b (4096^3 fp32) via mma.sync.m16n8k16.f32.f16.f16.f32.
//
// Round-5: CTA tile 256x128, 8 warps (4x2 grid of 64x64 warp tiles),
// 1 CTA/SM, 6-stage cp.async pipeline. Halves smem-crossbar pressure
// (64 B/cyc vs the 128 B/cyc ceiling round 4 sat at).
//
// Pre-pass converts fp32 -> fp16 (RN) and permutes into exact mma fragment
// order so the mainloop is: linear cp.async + LDS.128/LDS.64 + mma only.
//   A'[m128][kb128][mt16:8][ks:2][lane:32][4xb32]
//   B'[n128][kb128][nt8:16][ks:2][lane:32][2xb32]
// ============================================================================

#define KDIM 4096
#define BK 32
#define STAGES 6
#define K_ITERS (KDIM / BK)               // 128
#define A_STAGE 16384                     // 256 x 32 x 2B
#define B_STAGE 8192                      // 128 x 32 x 2B
#define STAGE_BYTES (A_STAGE + B_STAGE)   // 24576
#define SMEM_TOTAL (STAGES * STAGE_BYTES) // 147456

#define MBLK_BYTES ((size_t)128 * KDIM * 2)   // one 128-row fragment block: 1MB

__device__ __half g_xa[(size_t)KDIM * KDIM];   // A' fragment-ordered fp16
__device__ __half g_wb[(size_t)KDIM * KDIM];   // B' fragment-ordered fp16

// ---------------------------------------------------------------------------
__device__ __forceinline__ uint32_t smem_u32(const void* p) {
    uint32_t a;
    asm("{ .reg .u64 t; cvta.to.shared.u64 t, %1; cvt.u32.u64 %0, t; }"
        : "=r"(a) : "l"(p));
    return a;
}
__device__ __forceinline__ void cp_async16(uint32_t dst, const void* src) {
    asm volatile("cp.async.cg.shared.global [%0], [%1], 16;"
                 :: "r"(dst), "l"(src) : "memory");
}
__device__ __forceinline__ void cp_commit() {
    asm volatile("cp.async.commit_group;" ::: "memory");
}
__device__ __forceinline__ void cp_wait() {
    asm volatile("cp.async.wait_group %0;" :: "n"(STAGES - 2) : "memory");
}
__device__ __forceinline__ void lds128(uint32_t* r, uint32_t a) {
    asm volatile("ld.shared.v4.b32 {%0,%1,%2,%3}, [%4];"
                 : "=r"(r[0]), "=r"(r[1]), "=r"(r[2]), "=r"(r[3]) : "r"(a));
}
__device__ __forceinline__ void lds64(uint32_t* r, uint32_t a) {
    asm volatile("ld.shared.v2.b32 {%0,%1}, [%2];"
                 : "=r"(r[0]), "=r"(r[1]) : "r"(a));
}
__device__ __forceinline__ void mma_f16(float* c, const uint32_t* a, const uint32_t* b) {
    asm volatile(
        "mma.sync.aligned.m16n8k16.row.col.f32.f16.f16.f32 "
        "{%0,%1,%2,%3}, {%4,%5,%6,%7}, {%8,%9}, {%0,%1,%2,%3};"
        : "+f"(c[0]), "+f"(c[1]), "+f"(c[2]), "+f"(c[3])
        : "r"(a[0]), "r"(a[1]), "r"(a[2]), "r"(a[3]), "r"(b[0]), "r"(b[1]));
}
__device__ __forceinline__ uint32_t pack_h2(float lo, float hi) {
    __half2 h = __floats2half2_rn(lo, hi);
    return *reinterpret_cast<uint32_t*>(&h);
}

// ---------------------------------------------------------------------------
// Pre-pass A: one 16B fragment (8 halves) per thread.
// idx bits: [m128:5][kb:7][mt16:3][ks:1][lane:5]
// ---------------------------------------------------------------------------
__global__ void __launch_bounds__(256) prep_a(const float* __restrict__ src,
                                              uint4* __restrict__ dst) {
    const int idx  = blockIdx.x * 256 + threadIdx.x;
    const int lane = idx & 31;
    const int ks   = (idx >> 5) & 1;
    const int mt16 = (idx >> 6) & 7;
    const int kb   = (idx >> 9) & 127;
    const int m128 = idx >> 16;
    const int row = m128 * 128 + mt16 * 16 + (lane >> 2);
    const int col = kb * 32 + ks * 16 + (lane & 3) * 2;
    const float* p = src + (size_t)row * KDIM + col;
    const float2 v00 = *reinterpret_cast<const float2*>(p);
    const float2 v10 = *reinterpret_cast<const float2*>(p + (size_t)8 * KDIM);
    const float2 v01 = *reinterpret_cast<const float2*>(p + 8);
    const float2 v11 = *reinterpret_cast<const float2*>(p + (size_t)8 * KDIM + 8);
    uint4 o;
    o.x = pack_h2(v00.x, v00.y);
    o.y = pack_h2(v10.x, v10.y);
    o.z = pack_h2(v01.x, v01.y);
    o.w = pack_h2(v11.x, v11.y);
    dst[idx] = o;
}

// Pre-pass B: one 8B fragment (4 halves) per thread.
// idx bits: [n128:5][kb:7][nt8:4][ks:1][lane:5]
__global__ void __launch_bounds__(256) prep_b(const float* __restrict__ src,
                                              uint2* __restrict__ dst) {
    const int idx  = blockIdx.x * 256 + threadIdx.x;
    const int lane = idx & 31;
    const int ks   = (idx >> 5) & 1;
    const int nt8  = (idx >> 6) & 15;
    const int kb   = (idx >> 10) & 127;
    const int n128 = idx >> 17;
    const int n = n128 * 128 + nt8 * 8 + (lane >> 2);
    const int k = kb * 32 + ks * 16 + (lane & 3) * 2;
    const float* p = src + (size_t)n * KDIM + k;
    const float2 v0 = *reinterpret_cast<const float2*>(p);
    const float2 v1 = *reinterpret_cast<const float2*>(p + 8);
    uint2 o;
    o.x = pack_h2(v0.x, v0.y);
    o.y = pack_h2(v1.x, v1.y);
    dst[idx] = o;
}

// ---------------------------------------------------------------------------
// GEMM: 256 threads, 8 warps (wm 0..3 x wn 0..1 of 64x64), 1 CTA/SM.
// ---------------------------------------------------------------------------
__global__ void __launch_bounds__(256, 1) gemm_f16_mma(
    const __half* __restrict__ Ap,
    const __half* __restrict__ Bp,
    const float* __restrict__ bias,
    float* __restrict__ out)
{
    extern __shared__ char smem[];
    const uint32_t sb = smem_u32(smem);

    const int tid  = threadIdx.x;
    const int lane = tid & 31;
    const int warp = tid >> 5;
    const int wm   = warp & 3;     // 4 warp rows (64 each) -> 256
    const int wn   = warp >> 2;    // 2 warp cols (64 each) -> 128

    const int m256 = blockIdx.x & 15;   // M fastest (B-tile L2 reuse)
    const int n128 = blockIdx.x >> 4;

    // Global fragment-block pointers. A' block = 128 rows; tile needs 2 blocks.
    const char* gA0 = (const char*)Ap + (size_t)(2 * m256)     * MBLK_BYTES + tid * 16;
    const char* gA1 = (const char*)Ap + (size_t)(2 * m256 + 1) * MBLK_BYTES + tid * 16;
    const char* gB  = (const char*)Bp + (size_t)n128           * MBLK_BYTES + tid * 16;

    // Fragment bases within a stage.
    const uint32_t aFragBase = sb + (uint32_t)(wm >> 1) * 8192
                                  + (uint32_t)(wm & 1) * 4096 + lane * 16;
    const uint32_t bFragBase = sb + A_STAGE + (uint32_t)wn * 4096 + lane * 8;

    float acc[4][8][4];
    #pragma unroll
    for (int i = 0; i < 4; i++)
        #pragma unroll
        for (int j = 0; j < 8; j++)
            #pragma unroll
            for (int r = 0; r < 4; r++) acc[i][j][r] = 0.f;

    // ---- prologue: fill STAGES-1 stages (6x 16B chunks per thread) ----
    #pragma unroll
    for (int s = 0; s < STAGES - 1; s++) {
        const uint32_t d = sb + s * STAGE_BYTES + tid * 16;
        const size_t ko = (size_t)s * 8192;
        #pragma unroll
        for (int i = 0; i < 2; i++) {
            cp_async16(d + i * 4096,                 gA0 + ko + i * 4096);
            cp_async16(d + 8192 + i * 4096,          gA1 + ko + i * 4096);
            cp_async16(d + A_STAGE + i * 4096,       gB  + ko + i * 4096);
        }
        cp_commit();
    }

    // ---- mainloop ----
    #pragma unroll 1
    for (int k = 0; k < K_ITERS; k++) {
        cp_wait();
        __syncthreads();

        if (k + STAGES - 1 < K_ITERS) {
            const int kf = k + STAGES - 1;
            const uint32_t d = sb + (kf % STAGES) * STAGE_BYTES + tid * 16;
            const size_t ko = (size_t)kf * 8192;
            #pragma unroll
            for (int i = 0; i < 2; i++) {
                cp_async16(d + i * 4096,           gA0 + ko + i * 4096);
                cp_async16(d + 8192 + i * 4096,    gA1 + ko + i * 4096);
                cp_async16(d + A_STAGE + i * 4096, gB  + ko + i * 4096);
            }
        }
        cp_commit();

        const uint32_t st = (uint32_t)(k % STAGES) * STAGE_BYTES;
        const uint32_t ab = aFragBase + st;
        const uint32_t bb = bFragBase + st;

        #pragma unroll
        for (int ks = 0; ks < 2; ks++) {
            uint32_t afr[4][4];
            uint32_t bfr[8][2];
            #pragma unroll
            for (int mt = 0; mt < 4; mt++)
                lds128(afr[mt], ab + mt * 1024 + ks * 512);
            #pragma unroll
            for (int nt = 0; nt < 8; nt++)
                lds64(bfr[nt], bb + nt * 512 + ks * 256);
            #pragma unroll
            for (int mt = 0; mt < 4; mt++)
                #pragma unroll
                for (int nt = 0; nt < 8; nt++)
                    mma_f16(acc[mt][nt], afr[mt], bfr[nt]);
        }
    }

    // ---- epilogue: bias + float2 stores ----
    const int fr = lane >> 2;
    const int orow0 = m256 * 256 + wm * 64 + fr;
    const int ocol0 = n128 * 128 + wn * 64 + 2 * (lane & 3);

    #pragma unroll
    for (int mt = 0; mt < 4; mt++) {
        #pragma unroll
        for (int nt = 0; nt < 8; nt++) {
            const int col = ocol0 + nt * 8;
            const float2 bv = *reinterpret_cast<const float2*>(bias + col);
            const int r0 = orow0 + mt * 16;
            float2 v0 = { acc[mt][nt][0] + bv.x, acc[mt][nt][1] + bv.y };
            float2 v1 = { acc[mt][nt][2] + bv.x, acc[mt][nt][3] + bv.y };
            *reinterpret_cast<float2*>(out + (size_t)r0 * KDIM + col) = v0;
            *reinterpret_cast<float2*>(out + (size_t)(r0 + 8) * KDIM + col) = v1;
        }
    }
}

// ---------------------------------------------------------------------------
extern "C" void kernel_launch(void* const* d_in, const int* in_sizes, int n_in,
                              void* d_out, int out_size) {
    const float* x    = (const float*)d_in[0];
    const float* w    = (const float*)d_in[1];
    const float* bias = (const float*)d_in[2];
    float* out        = (float*)d_out;

    void* gx = nullptr;
    void* gw = nullptr;
    cudaGetSymbolAddress(&gx, g_xa);
    cudaGetSymbolAddress(&gw, g_wb);

    static bool attr_set = false;  // host-side only
    if (!attr_set) {
        cudaFuncSetAttribute(gemm_f16_mma,
                             cudaFuncAttributeMaxDynamicSharedMemorySize, SMEM_TOTAL);
        attr_set = true;
    }

    prep_a<<<8192, 256>>>(x, (uint4*)gx);
    prep_b<<<16384, 256>>>(w, (uint2*)gw);

    // 16 M-tiles x 32 N-tiles = 512 CTAs, 1 per SM.
    gemm_f16_mma<<<512, 256, SMEM_TOTAL>>>((const __half*)gx, (const __half*)gw,
                                           bias, out);
}